// round 15
// baseline (speedup 1.0000x reference)
#include <cuda_runtime.h>
#include <cstdint>

// Fixed problem shapes
#define NIMG      262144     // 4096 * 64 images
#define IMG_ELEMS 128        // 16 x 8
#define IMG_W     8
#define OUT_ELEMS 84         // 14 x 6
#define OUT_W     6

#define THREADS   224                      // 7 warps: warp = row-group, lane = image
#define IMGS      32                       // images per tile
#define NTILES    (NIMG / IMGS)            // 8192

// Input smem: 33 float4 (132 floats) per image -> conflict-free LDS.128.
// After compute, words [img*132 + g*12, +12) are reused to stage outputs.
#define PAD_F4   33
#define PAD_F    132

#define NSM           148
#define BLOCKS_PER_SM 6
#define GRID          (NSM * BLOCKS_PER_SM)   // 888 persistent blocks

#define F4_PER_TILE (IMGS * IMG_ELEMS / 4)     // 1024
#define OUT_F4_PER_TILE (IMGS * OUT_ELEMS / 4) // 672 = 3 * 224
#define OUT_F4   (OUT_ELEMS / 4)               // 21

// Dynamic work queue: one atomic claims a PAIR of consecutive tiles.
__device__ unsigned int g_counter = 0;
__device__ unsigned int g_done    = 0;

__device__ __forceinline__ void cpasync16(uint32_t saddr, const void* g) {
    asm volatile("cp.async.cg.shared.global [%0], [%1], 16;\n"
                 :: "r"(saddr), "l"(g));
}
__device__ __forceinline__ void cp_commit() {
    asm volatile("cp.async.commit_group;\n");
}
__device__ __forceinline__ void cp_wait0() {
    asm volatile("cp.async.wait_group 0;\n");
}

__device__ __forceinline__ void loadrow(float* d, const float* p) {
    float4 lo = *(const float4*)p;
    float4 hi = *(const float4*)(p + 4);
    d[0] = lo.x; d[1] = lo.y; d[2] = lo.z; d[3] = lo.w;
    d[4] = hi.x; d[5] = hi.y; d[6] = hi.z; d[7] = hi.w;
}

__global__ __launch_bounds__(THREADS, BLOCKS_PER_SM)
void conv3x3_relu_kernel(const float* __restrict__ x,
                         const float* __restrict__ kern,
                         float* __restrict__ out)
{
    __shared__ float si[2][IMGS * PAD_F];   // 2 x 16896 B = 33792 B total
    __shared__ unsigned int s_next;

    const int tid = threadIdx.x;

    // Thread role: image = lane, 2-output-row group = warp (0..6)
    const int g   = tid >> 5;             // warp-uniform row group
    const int img = tid & 31;             // lane -> conflict-free LDS (stride 132)

    const float k0 = kern[0], k1 = kern[1], k2 = kern[2];
    const float k3 = kern[3], k4 = kern[4], k5 = kern[5];
    const float k6 = kern[6], k7 = kern[7], k8 = kern[8];

    const uint32_t sb0 = (uint32_t)__cvta_generic_to_shared(&si[0][0]);
    const uint32_t sb1 = (uint32_t)__cvta_generic_to_shared(&si[1][0]);

    float4* const si4[2] = { (float4*)&si[0][0], (float4*)&si[1][0] };
    const int oslot = img * PAD_F4 + g * 3;   // staging f4 index within a stage

    // ---- Claim first tile PAIR ----
    if (tid == 0) s_next = atomicAdd(&g_counter, 1u);
    __syncthreads();
    unsigned int t0 = 2u * s_next;
    unsigned int t1 = t0 + 1u;

    // ---- Prefetch t0 into buffer 0 ----
    if (t0 < NTILES) {
        const float4* src = (const float4*)(x + (long long)t0 * IMGS * IMG_ELEMS);
#pragma unroll
        for (int it = 0; it < 5; it++) {
            int i = tid + it * THREADS;
            if (i < F4_PER_TILE) {
                int im = i >> 5, w = i & 31;
                cpasync16(sb0 + (uint32_t)(im * PAD_F4 + w) * 16, src + i);
            }
        }
    }
    cp_commit();

    bool     stash_valid = false;
    unsigned stash = 0;
    bool     prev_valid = false;
    unsigned prev_tile = 0;

    int cur = 0;
    while (t0 < NTILES) {
        cp_wait0();           // t0's data resident in si[cur]
        __syncthreads();      // barrier A: input visible; prev iter's staging
                              //            of si[cur^1] complete -> flush safe

        // ---- Flush tile n-1 outputs from si[cur^1] (staged layout) ----
        if (prev_valid) {
            const float4* s4 = si4[cur ^ 1];
            float4* __restrict__ out4 =
                (float4*)(out + (long long)prev_tile * IMGS * OUT_ELEMS);
#pragma unroll
            for (int it = 0; it < OUT_F4_PER_TILE / THREADS; it++) {
                int i = tid + it * THREADS;      // [0, 672)
                int im = i / OUT_F4;             // /21
                int w  = i - im * OUT_F4;
                __stcs(out4 + i, s4[im * PAD_F4 + w]);
            }
        }

        __syncthreads();      // barrier C: flush reads of si[cur^1] done

        // ---- Prefetch t1 into si[cur^1] (overlaps compute below) ----
        if (t1 < NTILES) {
            const uint32_t sb = cur ? sb0 : sb1;
            const float4* src = (const float4*)(x + (long long)t1 * IMGS * IMG_ELEMS);
#pragma unroll
            for (int it = 0; it < 5; it++) {
                int i = tid + it * THREADS;
                if (i < F4_PER_TILE) {
                    int im = i >> 5, w = i & 31;
                    cpasync16(sb + (uint32_t)(im * PAD_F4 + w) * 16, src + i);
                }
            }
        }
        cp_commit();          // exactly one group per iteration

        // ---- Compute t0 from si[cur] ----
        float4 o0, o1, o2;
        {
            const float* base = &si[cur][0] + img * PAD_F + 2 * g * IMG_W;

            float a[8], b[8], c[8], d[8];
            loadrow(a, base);
            loadrow(b, base + IMG_W);
            loadrow(c, base + 2 * IMG_W);
            loadrow(d, base + 3 * IMG_W);

#define CONV9(r0, r1, r2, cc) \
    fmaxf(fmaf(r2[(cc)+2], k8, fmaf(r2[(cc)+1], k7, fmaf(r2[(cc)], k6, \
          fmaf(r1[(cc)+2], k5, fmaf(r1[(cc)+1], k4, fmaf(r1[(cc)], k3, \
          fmaf(r0[(cc)+2], k2, fmaf(r0[(cc)+1], k1, r0[(cc)] * k0)))))))), 0.0f)

            o0.x = CONV9(a, b, c, 0);
            o0.y = CONV9(a, b, c, 1);
            o0.z = CONV9(a, b, c, 2);
            o0.w = CONV9(a, b, c, 3);
            o1.x = CONV9(a, b, c, 4);
            o1.y = CONV9(a, b, c, 5);
            o1.z = CONV9(b, c, d, 0);
            o1.w = CONV9(b, c, d, 1);
            o2.x = CONV9(b, c, d, 2);
            o2.y = CONV9(b, c, d, 3);
            o2.z = CONV9(b, c, d, 4);
            o2.w = CONV9(b, c, d, 5);
#undef CONV9
        }

        // ---- Acquire t2: stash or fresh pair grab ----
        const bool need_grab = !stash_valid && (t1 < NTILES);
        if (tid == 0 && need_grab) s_next = atomicAdd(&g_counter, 1u);

        __syncthreads();      // barrier B: all compute reads of si[cur] done;
                              //            s_next visible

        unsigned int t2;
        if (stash_valid) {
            t2 = stash;
            stash_valid = false;
        } else if (t1 < NTILES) {
            const unsigned int base2 = 2u * s_next;
            t2 = base2;
            stash = base2 + 1u;
            stash_valid = true;
        } else {
            t2 = NTILES;
        }

        // ---- Stage outputs into the retired input buffer si[cur] ----
        // f4 index img*33 + g*3 -> bank group (img + 3g) mod 8: conflict-free
        {
            float4* sdst = si4[cur] + oslot;
            sdst[0] = o0;
            sdst[1] = o1;
            sdst[2] = o2;
        }
        // (staging fenced from next iter's flush by barrier A there)

        prev_valid = true;
        prev_tile  = t0;
        t0 = t1;
        t1 = t2;
        cur ^= 1;
    }

    // ---- Epilogue: flush the final staged tile (in si[cur^1] after flip) ----
    __syncthreads();
    if (prev_valid) {
        const float4* s4 = si4[cur ^ 1];
        float4* __restrict__ out4 =
            (float4*)(out + (long long)prev_tile * IMGS * OUT_ELEMS);
#pragma unroll
        for (int it = 0; it < OUT_F4_PER_TILE / THREADS; it++) {
            int i = tid + it * THREADS;
            int im = i / OUT_F4;
            int w  = i - im * OUT_F4;
            __stcs(out4 + i, s4[im * PAD_F4 + w]);
        }
    }

    // ---- Last block resets the queue for the next (graph-replayed) launch ----
    __syncthreads();
    if (tid == 0) {
        __threadfence();
        unsigned int d = atomicAdd(&g_done, 1u);
        if (d == GRID - 1) {
            g_counter = 0;
            g_done    = 0;
            __threadfence();
        }
    }
}

extern "C" void kernel_launch(void* const* d_in, const int* in_sizes, int n_in,
                              void* d_out, int out_size)
{
    const float* x    = (const float*)d_in[0];   // [4096, 64, 128]
    const float* kern = (const float*)d_in[1];   // [3, 3]
    float* out        = (float*)d_out;           // [4096, 64, 84]

    conv3x3_relu_kernel<<<GRID, THREADS>>>(x, kern, out);
}

// round 16
// speedup vs baseline: 1.0117x; 1.0117x over previous
#include <cuda_runtime.h>
#include <cstdint>

// Fixed problem shapes
#define NIMG      262144     // 4096 * 64 images
#define IMG_ELEMS 128        // 16 x 8
#define IMG_W     8
#define OUT_ELEMS 84         // 14 x 6
#define OUT_W     6

#define THREADS   224                      // 7 warps: warp = row-group, lane = image
#define IMGS      32                       // images per tile
#define NTILES    (NIMG / IMGS)            // 8192

// Input smem: 33 float4 (132 floats) per image -> conflict-free LDS.128
#define PAD_F4   33
#define PAD_F    132

#define NSM           148
#define BLOCKS_PER_SM 5
#define GRID          (NSM * BLOCKS_PER_SM)   // 740 persistent blocks

#define F4_PER_TILE (IMGS * IMG_ELEMS / 4)     // 1024
#define OUT_F4_PER_TILE (IMGS * OUT_ELEMS / 4) // 672 = 3 * 224
#define OUT_F4   (OUT_ELEMS / 4)               // 21

// Dynamic work queue: one atomic claims a PAIR of consecutive tiles.
__device__ unsigned int g_counter = 0;
__device__ unsigned int g_done    = 0;

__device__ __forceinline__ void cpasync16(uint32_t saddr, const void* g) {
    asm volatile("cp.async.cg.shared.global [%0], [%1], 16;\n"
                 :: "r"(saddr), "l"(g));
}
__device__ __forceinline__ void cp_commit() {
    asm volatile("cp.async.commit_group;\n");
}
__device__ __forceinline__ void cp_wait1() {
    asm volatile("cp.async.wait_group 1;\n");
}

__device__ __forceinline__ void loadrow(float* d, const float* p) {
    float4 lo = *(const float4*)p;
    float4 hi = *(const float4*)(p + 4);
    d[0] = lo.x; d[1] = lo.y; d[2] = lo.z; d[3] = lo.w;
    d[4] = hi.x; d[5] = hi.y; d[6] = hi.z; d[7] = hi.w;
}

__global__ __launch_bounds__(THREADS, BLOCKS_PER_SM)
void conv3x3_relu_kernel(const float* __restrict__ x,
                         const float* __restrict__ kern,
                         float* __restrict__ out)
{
    __shared__ float si[2][IMGS * PAD_F];   // 2 x 16896 B
    __shared__ float so[IMGS * OUT_ELEMS];  // 10752 B
    __shared__ unsigned int s_next;

    const int tid = threadIdx.x;

    // Thread role: image = lane, 2-output-row group = warp (0..6)
    const int g   = tid >> 5;             // warp-uniform row group
    const int img = tid & 31;             // lane -> conflict-free LDS (stride 132)

    const float k0 = kern[0], k1 = kern[1], k2 = kern[2];
    const float k3 = kern[3], k4 = kern[4], k5 = kern[5];
    const float k6 = kern[6], k7 = kern[7], k8 = kern[8];

    const uint32_t sb0 = (uint32_t)__cvta_generic_to_shared(&si[0][0]);
    const uint32_t sb1 = (uint32_t)__cvta_generic_to_shared(&si[1][0]);

    float4* const so4 = (float4*)so;
    float4* const odst4 = so4 + img * OUT_F4 + g * 3;

    // ---- Claim first tile PAIR: t0 (current) and t1 (next) ----
    if (tid == 0) s_next = atomicAdd(&g_counter, 1u);
    __syncthreads();
    unsigned int t0 = 2u * s_next;        // uniform across block
    unsigned int t1 = t0 + 1u;

    // ---- Prefetch t0 into buffer 0 ----
    if (t0 < NTILES) {
        const float4* src = (const float4*)(x + (long long)t0 * IMGS * IMG_ELEMS);
#pragma unroll
        for (int it = 0; it < 5; it++) {
            int i = tid + it * THREADS;
            if (i < F4_PER_TILE) {
                int im = i >> 5, w = i & 31;
                cpasync16(sb0 + (uint32_t)(im * PAD_F4 + w) * 16, src + i);
            }
        }
    }
    cp_commit();

    // Stash of the second tile from the most recent pair grab (uniform regs)
    bool     stash_valid = false;
    unsigned stash = 0;

    int cur = 0;
    while (t0 < NTILES) {
        // ---- Prefetch t1 into the other buffer ----
        if (t1 < NTILES) {
            const uint32_t sb = cur ? sb0 : sb1;
            const float4* src = (const float4*)(x + (long long)t1 * IMGS * IMG_ELEMS);
#pragma unroll
            for (int it = 0; it < 5; it++) {
                int i = tid + it * THREADS;
                if (i < F4_PER_TILE) {
                    int im = i >> 5, w = i & 31;
                    cpasync16(sb + (uint32_t)(im * PAD_F4 + w) * 16, src + i);
                }
            }
        }
        cp_commit();          // commit (possibly empty) group every iteration
        cp_wait1();           // t0's group (older) is complete
        __syncthreads();      // barrier A: buffer visible; so[] reusable;
                              //            prev iter's s_next read ordered
                              //            before this iter's write

        // ---- Early queue grab (tid 0): overlaps the entire compute phase.
        //      Result consumed only after barrier B. ----
        const bool need_grab = !stash_valid && (t1 < NTILES);
        if (tid == 0 && need_grab) s_next = atomicAdd(&g_counter, 1u);

        // ---- Compute t0 from si[cur]: 2 output rows (12 floats) per thread ----
        {
            const float* base = &si[cur][0] + img * PAD_F + 2 * g * IMG_W;

            float a[8], b[8], c[8], d[8];
            loadrow(a, base);
            loadrow(b, base + IMG_W);
            loadrow(c, base + 2 * IMG_W);
            loadrow(d, base + 3 * IMG_W);

#define CONV9(r0, r1, r2, cc) \
    fmaxf(fmaf(r2[(cc)+2], k8, fmaf(r2[(cc)+1], k7, fmaf(r2[(cc)], k6, \
          fmaf(r1[(cc)+2], k5, fmaf(r1[(cc)+1], k4, fmaf(r1[(cc)], k3, \
          fmaf(r0[(cc)+2], k2, fmaf(r0[(cc)+1], k1, r0[(cc)] * k0)))))))), 0.0f)

            float4 o0, o1, o2;
            o0.x = CONV9(a, b, c, 0);
            o0.y = CONV9(a, b, c, 1);
            o0.z = CONV9(a, b, c, 2);
            o0.w = CONV9(a, b, c, 3);
            o1.x = CONV9(a, b, c, 4);
            o1.y = CONV9(a, b, c, 5);
            o1.z = CONV9(b, c, d, 0);
            o1.w = CONV9(b, c, d, 1);
            o2.x = CONV9(b, c, d, 2);
            o2.y = CONV9(b, c, d, 3);
            o2.z = CONV9(b, c, d, 4);
            o2.w = CONV9(b, c, d, 5);
#undef CONV9

            odst4[0] = o0;      // 3 x STS.128, bank-clean
            odst4[1] = o1;
            odst4[2] = o2;
        }

        __syncthreads();   // barrier B: staging done; si[cur] reads finished;
                           //            s_next update visible

        unsigned int t2;
        if (stash_valid) {
            t2 = stash;                    // uniform
            stash_valid = false;
        } else if (t1 < NTILES) {
            const unsigned int base2 = 2u * s_next;
            t2 = base2;
            stash = base2 + 1u;
            stash_valid = true;
        } else {
            t2 = NTILES;                   // sentinel: no more work
        }

        // ---- Flush: contiguous LDS.128 -> streaming STG.128 (3 iters) ----
        {
            float4* __restrict__ out4 =
                (float4*)(out + (long long)t0 * IMGS * OUT_ELEMS);
#pragma unroll
            for (int it = 0; it < OUT_F4_PER_TILE / THREADS; it++) {
                int i = tid + it * THREADS;      // [0, 672)
                __stcs(out4 + i, so4[i]);
            }
        }

        t0 = t1;
        t1 = t2;
        cur ^= 1;
    }

    // ---- Last block resets the queue for the next (graph-replayed) launch ----
    __syncthreads();
    if (tid == 0) {
        __threadfence();
        unsigned int d = atomicAdd(&g_done, 1u);
        if (d == GRID - 1) {
            g_counter = 0;
            g_done    = 0;
            __threadfence();
        }
    }
}

extern "C" void kernel_launch(void* const* d_in, const int* in_sizes, int n_in,
                              void* d_out, int out_size)
{
    const float* x    = (const float*)d_in[0];   // [4096, 64, 128]
    const float* kern = (const float*)d_in[1];   // [3, 3]
    float* out        = (float*)d_out;           // [4096, 64, 84]

    conv3x3_relu_kernel<<<GRID, THREADS>>>(x, kern, out);
}

// round 17
// speedup vs baseline: 1.0519x; 1.0398x over previous
#include <cuda_runtime.h>
#include <cstdint>

// Fixed problem shapes
#define NIMG      262144     // 4096 * 64 images
#define IMG_ELEMS 128        // 16 x 8
#define IMG_W     8
#define OUT_ELEMS 84         // 14 x 6
#define OUT_W     6

#define THREADS   224                      // 7 warps: warp = row-group, lane = image
#define IMGS      32                       // images per tile
#define NTILES    (NIMG / IMGS)            // 8192

// Input smem: 33 float4 (132 floats) per image -> conflict-free LDS.128
#define PAD_F4   33
#define PAD_F    132

#define NSM           148
#define BLOCKS_PER_SM 5
#define GRID          (NSM * BLOCKS_PER_SM)   // 740 persistent blocks

#define F4_PER_TILE (IMGS * IMG_ELEMS / 4)     // 1024
#define OUT_F4_PER_TILE (IMGS * OUT_ELEMS / 4) // 672 = 3 * 224
#define OUT_F4   (OUT_ELEMS / 4)               // 21

// Dynamic work queue: one atomic claims a PAIR of consecutive tiles.
__device__ unsigned int g_counter = 0;
__device__ unsigned int g_done    = 0;

__device__ __forceinline__ void cpasync16(uint32_t saddr, const void* g) {
    asm volatile("cp.async.cg.shared.global [%0], [%1], 16;\n"
                 :: "r"(saddr), "l"(g));
}
__device__ __forceinline__ void cp_commit() {
    asm volatile("cp.async.commit_group;\n");
}
__device__ __forceinline__ void cp_wait1() {
    asm volatile("cp.async.wait_group 1;\n");
}

__device__ __forceinline__ void loadrow(float* d, const float* p) {
    float4 lo = *(const float4*)p;
    float4 hi = *(const float4*)(p + 4);
    d[0] = lo.x; d[1] = lo.y; d[2] = lo.z; d[3] = lo.w;
    d[4] = hi.x; d[5] = hi.y; d[6] = hi.z; d[7] = hi.w;
}

__global__ __launch_bounds__(THREADS, BLOCKS_PER_SM)
void conv3x3_relu_kernel(const float* __restrict__ x,
                         const float* __restrict__ kern,
                         float* __restrict__ out)
{
    __shared__ float si[2][IMGS * PAD_F];   // 2 x 16896 B
    __shared__ float so[IMGS * OUT_ELEMS];  // 10752 B
    __shared__ unsigned int s_next;

    const int tid = threadIdx.x;

    // Thread role: image = lane, 2-output-row group = warp (0..6)
    const int g   = tid >> 5;             // warp-uniform row group
    const int img = tid & 31;             // lane -> conflict-free LDS (stride 132)

    const float k0 = kern[0], k1 = kern[1], k2 = kern[2];
    const float k3 = kern[3], k4 = kern[4], k5 = kern[5];
    const float k6 = kern[6], k7 = kern[7], k8 = kern[8];

    const uint32_t sb0 = (uint32_t)__cvta_generic_to_shared(&si[0][0]);
    const uint32_t sb1 = (uint32_t)__cvta_generic_to_shared(&si[1][0]);

    float4* const so4 = (float4*)so;
    float4* const odst4 = so4 + img * OUT_F4 + g * 3;

    // ---- Claim first tile PAIR: t0 (current) and t1 (next) ----
    if (tid == 0) s_next = atomicAdd(&g_counter, 1u);
    __syncthreads();
    unsigned int t0 = 2u * s_next;        // uniform across block
    unsigned int t1 = t0 + 1u;

    // ---- Prefetch t0 into buffer 0 ----
    if (t0 < NTILES) {
        const float4* src = (const float4*)(x + (long long)t0 * IMGS * IMG_ELEMS);
#pragma unroll
        for (int it = 0; it < 5; it++) {
            int i = tid + it * THREADS;
            if (i < F4_PER_TILE) {
                int im = i >> 5, w = i & 31;
                cpasync16(sb0 + (uint32_t)(im * PAD_F4 + w) * 16, src + i);
            }
        }
    }
    cp_commit();

    // Stash of the second tile from the most recent pair grab (uniform regs)
    bool     stash_valid = false;
    unsigned stash = 0;

    int cur = 0;
    while (t0 < NTILES) {
        // ---- Prefetch t1 into the other buffer ----
        if (t1 < NTILES) {
            const uint32_t sb = cur ? sb0 : sb1;
            const float4* src = (const float4*)(x + (long long)t1 * IMGS * IMG_ELEMS);
#pragma unroll
            for (int it = 0; it < 5; it++) {
                int i = tid + it * THREADS;
                if (i < F4_PER_TILE) {
                    int im = i >> 5, w = i & 31;
                    cpasync16(sb + (uint32_t)(im * PAD_F4 + w) * 16, src + i);
                }
            }
        }
        cp_commit();          // commit (possibly empty) group every iteration
        cp_wait1();           // t0's group (older) is complete
        __syncthreads();      // barrier A: buffer visible; so[] reusable

        // ---- Compute t0 from si[cur]: 2 output rows (12 floats) per thread ----
        {
            const float* base = &si[cur][0] + img * PAD_F + 2 * g * IMG_W;

            float a[8], b[8], c[8], d[8];
            loadrow(a, base);
            loadrow(b, base + IMG_W);
            loadrow(c, base + 2 * IMG_W);
            loadrow(d, base + 3 * IMG_W);

#define CONV9(r0, r1, r2, cc) \
    fmaxf(fmaf(r2[(cc)+2], k8, fmaf(r2[(cc)+1], k7, fmaf(r2[(cc)], k6, \
          fmaf(r1[(cc)+2], k5, fmaf(r1[(cc)+1], k4, fmaf(r1[(cc)], k3, \
          fmaf(r0[(cc)+2], k2, fmaf(r0[(cc)+1], k1, r0[(cc)] * k0)))))))), 0.0f)

            float4 o0, o1, o2;
            o0.x = CONV9(a, b, c, 0);
            o0.y = CONV9(a, b, c, 1);
            o0.z = CONV9(a, b, c, 2);
            o0.w = CONV9(a, b, c, 3);
            o1.x = CONV9(a, b, c, 4);
            o1.y = CONV9(a, b, c, 5);
            o1.z = CONV9(b, c, d, 0);
            o1.w = CONV9(b, c, d, 1);
            o2.x = CONV9(b, c, d, 2);
            o2.y = CONV9(b, c, d, 3);
            o2.z = CONV9(b, c, d, 4);
            o2.w = CONV9(b, c, d, 5);
#undef CONV9

            odst4[0] = o0;      // 3 x STS.128, bank-clean
            odst4[1] = o1;
            odst4[2] = o2;
        }

        // ---- Acquire t2: from stash, or grab a fresh pair (tid 0) ----
        const bool need_grab = !stash_valid && (t1 < NTILES);
        if (tid == 0 && need_grab) s_next = atomicAdd(&g_counter, 1u);

        __syncthreads();   // barrier B: staging done; si[cur] reads finished;
                           //            s_next update visible

        unsigned int t2;
        if (stash_valid) {
            t2 = stash;                    // uniform
            stash_valid = false;
        } else if (t1 < NTILES) {
            const unsigned int base2 = 2u * s_next;
            t2 = base2;
            stash = base2 + 1u;
            stash_valid = true;
        } else {
            t2 = NTILES;                   // sentinel: no more work
        }

        // ---- Flush: contiguous LDS.128 -> coalesced STG.128 (3 iters) ----
        // Plain stores (no evict-first hint): let L2 batch full-line writebacks
        // from the dense per-tile burst.
        {
            float4* __restrict__ out4 =
                (float4*)(out + (long long)t0 * IMGS * OUT_ELEMS);
#pragma unroll
            for (int it = 0; it < OUT_F4_PER_TILE / THREADS; it++) {
                int i = tid + it * THREADS;      // [0, 672)
                out4[i] = so4[i];
            }
        }

        t0 = t1;
        t1 = t2;
        cur ^= 1;
    }

    // ---- Last block resets the queue for the next (graph-replayed) launch ----
    __syncthreads();
    if (tid == 0) {
        __threadfence();
        unsigned int d = atomicAdd(&g_done, 1u);
        if (d == GRID - 1) {
            g_counter = 0;
            g_done    = 0;
            __threadfence();
        }
    }
}

extern "C" void kernel_launch(void* const* d_in, const int* in_sizes, int n_in,
                              void* d_out, int out_size)
{
    const float* x    = (const float*)d_in[0];   // [4096, 64, 128]
    const float* kern = (const float*)d_in[1];   // [3, 3]
    float* out        = (float*)d_out;           // [4096, 64, 84]

    conv3x3_relu_kernel<<<GRID, THREADS>>>(x, kern, out);
}